// round 1
// baseline (speedup 1.0000x reference)
#include <cuda_runtime.h>
#include <float.h>

#define DK 32
#define ODIM 32
#define MAX_NODES 100002

// Scratch: CSR row pointers (device global — no allocation allowed in kernel_launch)
__device__ int g_row_ptr[MAX_NODES];

// Kernel 1: build row pointers from sorted dst.
// g_row_ptr[n] = first edge index e with dst[e] >= n; g_row_ptr[N] = E.
__global__ void build_row_ptr_kernel(const int* __restrict__ dst, int E, int N) {
    int e = blockIdx.x * blockDim.x + threadIdx.x;
    if (e >= E) return;
    int d = dst[e];
    if (e == 0) {
        for (int n = 0; n <= d; ++n) g_row_ptr[n] = 0;
    } else {
        int dp = dst[e - 1];
        for (int n = dp + 1; n <= d; ++n) g_row_ptr[n] = e;
    }
    if (e == E - 1) {
        for (int n = d + 1; n <= N; ++n) g_row_ptr[n] = E;
    }
}

// Kernel 2: one warp per dst node. Online (flash) segment softmax + V aggregation
// + fused 32x32 output projection.
__global__ __launch_bounds__(256) void gat_warp_kernel(
    const float* __restrict__ X,
    const float* __restrict__ Kf,
    const float* __restrict__ Vf,
    const float* __restrict__ Wo,
    const float* __restrict__ bo,
    const int*   __restrict__ src,
    float* __restrict__ out,
    int N)
{
    const unsigned FULL = 0xffffffffu;
    int warp = (blockIdx.x * blockDim.x + threadIdx.x) >> 5;
    int lane = threadIdx.x & 31;
    if (warp >= N) return;
    const int node = warp;

    const int beg = g_row_ptr[node];
    const int end = g_row_ptr[node + 1];

    // Query row X[node] in registers (all lanes identical -> broadcast loads)
    const float4* xq = reinterpret_cast<const float4*>(X + (size_t)node * DK);
    float4 q0 = xq[0], q1 = xq[1], q2 = xq[2], q3 = xq[3];
    float4 q4 = xq[4], q5 = xq[5], q6 = xq[6], q7 = xq[7];

    float m = -FLT_MAX;   // running max
    float l = 0.0f;       // running exp-sum
    float acc = 0.0f;     // lane holds dim `lane` of weighted V sum

    for (int base = beg; base < end; base += 32) {
        const int e = base + lane;
        const bool valid = (e < end);
        int sj = 0;
        float s = -FLT_MAX;
        if (valid) {
            sj = src[e];
            const float4* kr = reinterpret_cast<const float4*>(Kf + (size_t)sj * DK);
            float4 k0 = kr[0], k1 = kr[1], k2 = kr[2], k3 = kr[3];
            float4 k4 = kr[4], k5 = kr[5], k6 = kr[6], k7 = kr[7];
            float dot = 0.0f;
            dot += q0.x*k0.x + q0.y*k0.y + q0.z*k0.z + q0.w*k0.w;
            dot += q1.x*k1.x + q1.y*k1.y + q1.z*k1.z + q1.w*k1.w;
            dot += q2.x*k2.x + q2.y*k2.y + q2.z*k2.z + q2.w*k2.w;
            dot += q3.x*k3.x + q3.y*k3.y + q3.z*k3.z + q3.w*k3.w;
            dot += q4.x*k4.x + q4.y*k4.y + q4.z*k4.z + q4.w*k4.w;
            dot += q5.x*k5.x + q5.y*k5.y + q5.z*k5.z + q5.w*k5.w;
            dot += q6.x*k6.x + q6.y*k6.y + q6.z*k6.z + q6.w*k6.w;
            dot += q7.x*k7.x + q7.y*k7.y + q7.z*k7.z + q7.w*k7.w;
            s = dot * (1.0f / DK);
        }

        // chunk max over warp
        float cm = s;
        #pragma unroll
        for (int o = 16; o; o >>= 1) cm = fmaxf(cm, __shfl_xor_sync(FULL, cm, o));
        const float mnew = fmaxf(m, cm);

        float p = valid ? __expf(s - mnew) : 0.0f;

        // chunk exp-sum
        float ps = p;
        #pragma unroll
        for (int o = 16; o; o >>= 1) ps += __shfl_xor_sync(FULL, ps, o);

        const float scale = __expf(m - mnew);  // 0 on first chunk (m=-FLT_MAX)
        l = l * scale + ps;
        acc *= scale;

        // V aggregation: broadcast each edge's weight + src, coalesced V row loads
        const int cnt = min(32, end - base);
        #pragma unroll 4
        for (int j = 0; j < cnt; ++j) {
            const float pj  = __shfl_sync(FULL, p, j);
            const int   sjj = __shfl_sync(FULL, sj, j);
            acc += pj * Vf[(size_t)sjj * DK + lane];
        }
        m = mnew;
    }

    if (l > 0.0f) acc *= (1.0f / l);

    // Fused output projection: out[node][lane] = sum_d acc_d * Wo[d][lane] + bo[lane]
    float o = 0.0f;
    #pragma unroll
    for (int d = 0; d < DK; ++d) {
        const float ad = __shfl_sync(FULL, acc, d);
        o += ad * Wo[d * ODIM + lane];
    }
    out[(size_t)node * ODIM + lane] = o + bo[lane];
}

extern "C" void kernel_launch(void* const* d_in, const int* in_sizes, int n_in,
                              void* d_out, int out_size) {
    const float* X   = (const float*)d_in[0];
    const float* K   = (const float*)d_in[1];
    const float* V   = (const float*)d_in[2];
    const float* Wo  = (const float*)d_in[3];
    const float* bo  = (const float*)d_in[4];
    const int*   src = (const int*)d_in[5];
    const int*   dst = (const int*)d_in[6];

    const int N = in_sizes[0] / DK;   // 100000
    const int E = in_sizes[5];        // 1600000

    build_row_ptr_kernel<<<(E + 255) / 256, 256>>>(dst, E, N);

    const int threads = 256;                 // 8 warps/block, 1 node/warp
    const int blocks  = (N * 32 + threads - 1) / threads;
    gat_warp_kernel<<<blocks, threads>>>(X, K, V, Wo, bo, src, (float*)d_out, N);
}

// round 2
// speedup vs baseline: 1.7485x; 1.7485x over previous
#include <cuda_runtime.h>

#define DK 32
#define ODIM 32
#define MAX_NODES 100002
#define NPW 8   // nodes per warp (amortizes Wo register cache)

// Scratch: CSR row pointers (device global — no allocation in kernel_launch)
__device__ int g_row_ptr[MAX_NODES];

// Kernel 1: build row pointers from sorted dst.
__global__ void build_row_ptr_kernel(const int* __restrict__ dst, int E, int N) {
    int e = blockIdx.x * blockDim.x + threadIdx.x;
    if (e >= E) return;
    int d = dst[e];
    if (e == 0) {
        for (int n = 0; n <= d; ++n) g_row_ptr[n] = 0;
    } else {
        int dp = dst[e - 1];
        for (int n = dp + 1; n <= d; ++n) g_row_ptr[n] = e;
    }
    if (e == E - 1) {
        for (int n = d + 1; n <= N; ++n) g_row_ptr[n] = E;
    }
}

// Kernel 2: one warp handles NPW nodes. 8-lane groups cooperatively fetch one
// K row + one V row per edge with single LDG.128s (1 L1 wavefront per row).
// No online max (scores bounded, exp-safe); single fused K+V pass per edge.
__global__ __launch_bounds__(256) void gat_kernel(
    const float* __restrict__ X,
    const float* __restrict__ Kf,
    const float* __restrict__ Vf,
    const float* __restrict__ Wo,
    const float* __restrict__ bo,
    const int*   __restrict__ src,
    float* __restrict__ out,
    int N)
{
    const unsigned FULL = 0xffffffffu;
    const int lane = threadIdx.x & 31;
    const int warp = (blockIdx.x * blockDim.x + threadIdx.x) >> 5;
    const int node0 = warp * NPW;
    if (node0 >= N) return;

    // Per-warp register cache of Wo column `lane` and bias.
    float wcol[DK];
    #pragma unroll
    for (int d = 0; d < DK; ++d) wcol[d] = __ldg(&Wo[d * ODIM + lane]);
    const float bval = __ldg(&bo[lane]);

    const int g  = lane >> 3;   // which edge of the 4-edge batch this lane serves
    const int qd = lane & 7;    // which float4 dim-quad this lane covers

    for (int ni = 0; ni < NPW; ++ni) {
        const int node = node0 + ni;
        if (node >= N) break;
        const int beg = g_row_ptr[node];
        const int end = g_row_ptr[node + 1];

        // This lane's quad of the query row (one 128B line per node).
        const float4 q4 = *reinterpret_cast<const float4*>(X + (size_t)node * DK + qd * 4);

        float4 acc = make_float4(0.f, 0.f, 0.f, 0.f);
        float lsum = 0.f;

        // 8 edges per iteration: two independent 4-edge sub-batches for MLP.
        for (int base = beg; base < end; base += 8) {
            const int eA = base + g;
            const int eB = base + 4 + g;
            const bool vA = (eA < end);
            const bool vB = (eB < end);
            const int sA = __ldg(&src[vA ? eA : beg]);
            const int sB = vB ? __ldg(&src[eB]) : 0;

            const float4 k4a = *(reinterpret_cast<const float4*>(Kf + (size_t)sA * DK) + qd);
            const float4 v4a = *(reinterpret_cast<const float4*>(Vf + (size_t)sA * DK) + qd);
            float4 k4b = make_float4(0.f, 0.f, 0.f, 0.f);
            float4 v4b = make_float4(0.f, 0.f, 0.f, 0.f);
            if (vB) {
                k4b = *(reinterpret_cast<const float4*>(Kf + (size_t)sB * DK) + qd);
                v4b = *(reinterpret_cast<const float4*>(Vf + (size_t)sB * DK) + qd);
            }

            float dA = q4.x*k4a.x + q4.y*k4a.y + q4.z*k4a.z + q4.w*k4a.w;
            float dB = q4.x*k4b.x + q4.y*k4b.y + q4.z*k4b.z + q4.w*k4b.w;
            // finish dot within the 8-lane group (xor on low 3 bits)
            #pragma unroll
            for (int o = 1; o <= 4; o <<= 1) {
                dA += __shfl_xor_sync(FULL, dA, o);
                dB += __shfl_xor_sync(FULL, dB, o);
            }
            const float pA = vA ? __expf(dA * (1.f / DK)) : 0.f;
            const float pB = vB ? __expf(dB * (1.f / DK)) : 0.f;
            lsum += pA + pB;

            acc.x += pA * v4a.x + pB * v4b.x;
            acc.y += pA * v4a.y + pB * v4b.y;
            acc.z += pA * v4a.z + pB * v4b.z;
            acc.w += pA * v4a.w + pB * v4b.w;
        }

        // Sum partial acc across the 4 edge-groups (xor 8, 16).
        #pragma unroll
        for (int o = 8; o <= 16; o <<= 1) {
            acc.x += __shfl_xor_sync(FULL, acc.x, o);
            acc.y += __shfl_xor_sync(FULL, acc.y, o);
            acc.z += __shfl_xor_sync(FULL, acc.z, o);
            acc.w += __shfl_xor_sync(FULL, acc.w, o);
        }
        // lsum: warp total counts each edge 8x.
        float l = lsum;
        #pragma unroll
        for (int o = 16; o; o >>= 1) l += __shfl_xor_sync(FULL, l, o);
        l *= 0.125f;
        const float inv = (l > 0.f) ? (1.f / l) : 0.f;
        acc.x *= inv; acc.y *= inv; acc.z *= inv; acc.w *= inv;

        // Projection: out[node][lane] = sum_d acc_d * Wo[d][lane] + b[lane].
        // acc quad qq lives (replicated) in lanes with (lane&7)==qq; lane qq works.
        float o = bval;
        #pragma unroll
        for (int qq = 0; qq < 8; ++qq) {
            const float ax = __shfl_sync(FULL, acc.x, qq);
            const float ay = __shfl_sync(FULL, acc.y, qq);
            const float az = __shfl_sync(FULL, acc.z, qq);
            const float aw = __shfl_sync(FULL, acc.w, qq);
            o += ax * wcol[4*qq+0] + ay * wcol[4*qq+1]
               + az * wcol[4*qq+2] + aw * wcol[4*qq+3];
        }
        out[(size_t)node * ODIM + lane] = o;
    }
}

extern "C" void kernel_launch(void* const* d_in, const int* in_sizes, int n_in,
                              void* d_out, int out_size) {
    const float* X   = (const float*)d_in[0];
    const float* K   = (const float*)d_in[1];
    const float* V   = (const float*)d_in[2];
    const float* Wo  = (const float*)d_in[3];
    const float* bo  = (const float*)d_in[4];
    const int*   src = (const int*)d_in[5];
    const int*   dst = (const int*)d_in[6];

    const int N = in_sizes[0] / DK;   // 100000
    const int E = in_sizes[5];        // 1600000

    build_row_ptr_kernel<<<(E + 255) / 256, 256>>>(dst, E, N);

    const int warps  = (N + NPW - 1) / NPW;      // 12500 warps
    const int threads = 256;
    const int blocks  = (warps * 32 + threads - 1) / threads;
    gat_kernel<<<blocks, threads>>>(X, K, V, Wo, bo, src, (float*)d_out, N);
}

// round 3
// speedup vs baseline: 1.8154x; 1.0383x over previous
#include <cuda_runtime.h>

#define DK 32
#define ODIM 32
#define MAX_NODES 100002
#define NPW 4   // nodes per warp

// Scratch: CSR row pointers (device global — no allocation in kernel_launch)
__device__ int g_row_ptr[MAX_NODES];

// Kernel 1: build row pointers from sorted dst.
__global__ void build_row_ptr_kernel(const int* __restrict__ dst, int E, int N) {
    int e = blockIdx.x * blockDim.x + threadIdx.x;
    if (e >= E) return;
    int d = dst[e];
    if (e == 0) {
        for (int n = 0; n <= d; ++n) g_row_ptr[n] = 0;
    } else {
        int dp = dst[e - 1];
        for (int n = dp + 1; n <= d; ++n) g_row_ptr[n] = e;
    }
    if (e == E - 1) {
        for (int n = d + 1; n <= N; ++n) g_row_ptr[n] = E;
    }
}

// Kernel 2: one warp handles NPW nodes. 8-lane groups fetch one K row + one V
// row per edge as single LDG.128s; 16 edges in flight per iteration.
__global__ __launch_bounds__(256, 4) void gat_kernel(
    const float* __restrict__ X,
    const float* __restrict__ Kf,
    const float* __restrict__ Vf,
    const float* __restrict__ Wo,
    const float* __restrict__ bo,
    const int*   __restrict__ src,
    float* __restrict__ out,
    int N)
{
    const unsigned FULL = 0xffffffffu;
    __shared__ float sWo[DK][ODIM];
    __shared__ float sBo[ODIM];

    // Block-cooperative fill of Wo/bias (all threads; before any early-out).
    for (int i = threadIdx.x; i < DK * ODIM; i += blockDim.x)
        sWo[i / ODIM][i % ODIM] = Wo[i];
    if (threadIdx.x < ODIM) sBo[threadIdx.x] = bo[threadIdx.x];
    __syncthreads();

    const int lane = threadIdx.x & 31;
    const int warp = (blockIdx.x * blockDim.x + threadIdx.x) >> 5;
    const int node0 = warp * NPW;
    if (node0 >= N) return;

    const int g  = lane >> 3;   // edge slot within a 4-edge sub-batch
    const int qd = lane & 7;    // float4 dim-quad this lane covers

    const float bval = sBo[lane];

    #pragma unroll
    for (int ni = 0; ni < NPW; ++ni) {
        const int node = node0 + ni;
        if (node >= N) break;
        const int beg = g_row_ptr[node];
        const int end = g_row_ptr[node + 1];

        const float4 q4 = *reinterpret_cast<const float4*>(X + (size_t)node * DK + qd * 4);

        float4 acc = make_float4(0.f, 0.f, 0.f, 0.f);
        float lsum = 0.f;

        // 16 edges per iteration: 4 independent sub-batches of 4 edges.
        for (int base = beg; base < end; base += 16) {
            int  eidx[4];
            bool vld[4];
            #pragma unroll
            for (int s = 0; s < 4; ++s) {
                const int e = base + s * 4 + g;
                vld[s]  = (e < end);
                eidx[s] = vld[s] ? e : beg;   // clamp: load valid garbage, p=0
            }
            int sidx[4];
            #pragma unroll
            for (int s = 0; s < 4; ++s) sidx[s] = __ldg(&src[eidx[s]]);

            float4 kq[4], vq[4];
            #pragma unroll
            for (int s = 0; s < 4; ++s) {
                kq[s] = *(reinterpret_cast<const float4*>(Kf + (size_t)sidx[s] * DK) + qd);
                vq[s] = *(reinterpret_cast<const float4*>(Vf + (size_t)sidx[s] * DK) + qd);
            }

            float d[4];
            #pragma unroll
            for (int s = 0; s < 4; ++s)
                d[s] = q4.x*kq[s].x + q4.y*kq[s].y + q4.z*kq[s].z + q4.w*kq[s].w;

            #pragma unroll
            for (int o = 1; o <= 4; o <<= 1) {
                #pragma unroll
                for (int s = 0; s < 4; ++s) d[s] += __shfl_xor_sync(FULL, d[s], o);
            }

            float p[4];
            #pragma unroll
            for (int s = 0; s < 4; ++s) {
                p[s] = vld[s] ? __expf(d[s] * (1.f / DK)) : 0.f;
                lsum += p[s];
            }

            #pragma unroll
            for (int s = 0; s < 4; ++s) {
                acc.x += p[s] * vq[s].x;
                acc.y += p[s] * vq[s].y;
                acc.z += p[s] * vq[s].z;
                acc.w += p[s] * vq[s].w;
            }
        }

        // Sum partial acc across the 4 edge-groups.
        #pragma unroll
        for (int o = 8; o <= 16; o <<= 1) {
            acc.x += __shfl_xor_sync(FULL, acc.x, o);
            acc.y += __shfl_xor_sync(FULL, acc.y, o);
            acc.z += __shfl_xor_sync(FULL, acc.z, o);
            acc.w += __shfl_xor_sync(FULL, acc.w, o);
        }
        // Warp total of lsum counts each edge 8x.
        float l = lsum;
        #pragma unroll
        for (int o = 16; o; o >>= 1) l += __shfl_xor_sync(FULL, l, o);
        l *= 0.125f;
        const float inv = (l > 0.f) ? (1.f / l) : 0.f;
        acc.x *= inv; acc.y *= inv; acc.z *= inv; acc.w *= inv;

        // Projection: out[node][lane] = sum_d acc_d * Wo[d][lane] + b[lane].
        float o = bval;
        #pragma unroll
        for (int qq = 0; qq < 8; ++qq) {
            const float ax = __shfl_sync(FULL, acc.x, qq);
            const float ay = __shfl_sync(FULL, acc.y, qq);
            const float az = __shfl_sync(FULL, acc.z, qq);
            const float aw = __shfl_sync(FULL, acc.w, qq);
            o += ax * sWo[4*qq+0][lane] + ay * sWo[4*qq+1][lane]
               + az * sWo[4*qq+2][lane] + aw * sWo[4*qq+3][lane];
        }
        out[(size_t)node * ODIM + lane] = o;
    }
}

extern "C" void kernel_launch(void* const* d_in, const int* in_sizes, int n_in,
                              void* d_out, int out_size) {
    const float* X   = (const float*)d_in[0];
    const float* K   = (const float*)d_in[1];
    const float* V   = (const float*)d_in[2];
    const float* Wo  = (const float*)d_in[3];
    const float* bo  = (const float*)d_in[4];
    const int*   src = (const int*)d_in[5];
    const int*   dst = (const int*)d_in[6];

    const int N = in_sizes[0] / DK;   // 100000
    const int E = in_sizes[5];        // 1600000

    build_row_ptr_kernel<<<(E + 255) / 256, 256>>>(dst, E, N);

    const int warps   = (N + NPW - 1) / NPW;      // 25000 warps
    const int threads = 256;
    const int blocks  = (warps * 32 + threads - 1) / threads;
    gat_kernel<<<blocks, threads>>>(X, K, V, Wo, bo, src, (float*)d_out, N);
}

// round 4
// speedup vs baseline: 2.0573x; 1.1333x over previous
#include <cuda_runtime.h>

#define DK 32
#define ODIM 32
#define MAX_NODES 100002
#define NPW 2            // nodes per warp
#define WPB 4            // warps per block (block = 128 threads)

// Scratch: CSR row pointers (device global — no allocation in kernel_launch)
__device__ int g_row_ptr[MAX_NODES];

// Kernel 1: build row pointers from sorted dst.
__global__ void build_row_ptr_kernel(const int* __restrict__ dst, int E, int N) {
    int e = blockIdx.x * blockDim.x + threadIdx.x;
    if (e >= E) return;
    int d = dst[e];
    if (e == 0) {
        for (int n = 0; n <= d; ++n) g_row_ptr[n] = 0;
    } else {
        int dp = dst[e - 1];
        for (int n = dp + 1; n <= d; ++n) g_row_ptr[n] = e;
    }
    if (e == E - 1) {
        for (int n = d + 1; n <= N; ++n) g_row_ptr[n] = E;
    }
}

// Kernel 2: warp handles NPW nodes. 8-lane groups fetch one K row + one V row
// per edge as single LDG.128s. 8 edges/iter (2 sub-batches) keeps regs low for
// higher occupancy. Lean epilogue via smem transpose.
__global__ __launch_bounds__(128, 10) void gat_kernel(
    const float* __restrict__ X,
    const float* __restrict__ Kf,
    const float* __restrict__ Vf,
    const float* __restrict__ Wo,
    const float* __restrict__ bo,
    const int*   __restrict__ src,
    float* __restrict__ out,
    int N)
{
    const unsigned FULL = 0xffffffffu;
    __shared__ float sWo[DK][ODIM];
    __shared__ float sBo[ODIM];
    __shared__ __align__(16) float sAgg[WPB][DK];

    // Cooperative fill (all threads, before any early-out).
    for (int i = threadIdx.x; i < DK * ODIM; i += blockDim.x)
        sWo[i / ODIM][i % ODIM] = Wo[i];
    if (threadIdx.x < ODIM) sBo[threadIdx.x] = bo[threadIdx.x];
    __syncthreads();

    const int lane = threadIdx.x & 31;
    const int wib  = threadIdx.x >> 5;
    const int warp = (blockIdx.x * blockDim.x + threadIdx.x) >> 5;
    const int node0 = warp * NPW;
    if (node0 >= N) return;

    const int g  = lane >> 3;   // edge slot within a 4-edge sub-batch
    const int qd = lane & 7;    // float4 dim-quad this lane covers
    const float bval = sBo[lane];

    #pragma unroll
    for (int ni = 0; ni < NPW; ++ni) {
        const int node = node0 + ni;
        if (node >= N) break;
        const int beg = g_row_ptr[node];
        const int end = g_row_ptr[node + 1];

        const float4 q4 = *reinterpret_cast<const float4*>(X + (size_t)node * DK + qd * 4);

        float4 acc = make_float4(0.f, 0.f, 0.f, 0.f);
        float lsum = 0.f;

        // Full (unmasked) iterations: 8 edges = 2 sub-batches of 4.
        int base = beg;
        for (; base + 8 <= end; base += 8) {
            const int sA = __ldg(&src[base + g]);
            const int sB = __ldg(&src[base + 4 + g]);

            const float4 kA = *(reinterpret_cast<const float4*>(Kf + (size_t)sA * DK) + qd);
            const float4 kB = *(reinterpret_cast<const float4*>(Kf + (size_t)sB * DK) + qd);
            const float4 vA = *(reinterpret_cast<const float4*>(Vf + (size_t)sA * DK) + qd);
            const float4 vB = *(reinterpret_cast<const float4*>(Vf + (size_t)sB * DK) + qd);

            float dA = q4.x*kA.x + q4.y*kA.y + q4.z*kA.z + q4.w*kA.w;
            float dB = q4.x*kB.x + q4.y*kB.y + q4.z*kB.z + q4.w*kB.w;
            #pragma unroll
            for (int o = 1; o <= 4; o <<= 1) {
                dA += __shfl_xor_sync(FULL, dA, o);
                dB += __shfl_xor_sync(FULL, dB, o);
            }
            const float pA = __expf(dA * (1.f / DK));
            const float pB = __expf(dB * (1.f / DK));
            lsum += pA + pB;
            acc.x += pA * vA.x + pB * vB.x;
            acc.y += pA * vA.y + pB * vB.y;
            acc.z += pA * vA.z + pB * vB.z;
            acc.w += pA * vA.w + pB * vB.w;
        }

        // One masked tail iteration.
        if (base < end) {
            const int eA = base + g;
            const int eB = base + 4 + g;
            const bool vldA = (eA < end);
            const bool vldB = (eB < end);
            const int sA = __ldg(&src[vldA ? eA : beg]);
            const int sB = __ldg(&src[vldB ? eB : beg]);

            const float4 kA = *(reinterpret_cast<const float4*>(Kf + (size_t)sA * DK) + qd);
            const float4 kB = *(reinterpret_cast<const float4*>(Kf + (size_t)sB * DK) + qd);
            const float4 vA = *(reinterpret_cast<const float4*>(Vf + (size_t)sA * DK) + qd);
            const float4 vB = *(reinterpret_cast<const float4*>(Vf + (size_t)sB * DK) + qd);

            float dA = q4.x*kA.x + q4.y*kA.y + q4.z*kA.z + q4.w*kA.w;
            float dB = q4.x*kB.x + q4.y*kB.y + q4.z*kB.z + q4.w*kB.w;
            #pragma unroll
            for (int o = 1; o <= 4; o <<= 1) {
                dA += __shfl_xor_sync(FULL, dA, o);
                dB += __shfl_xor_sync(FULL, dB, o);
            }
            const float pA = vldA ? __expf(dA * (1.f / DK)) : 0.f;
            const float pB = vldB ? __expf(dB * (1.f / DK)) : 0.f;
            lsum += pA + pB;
            acc.x += pA * vA.x + pB * vB.x;
            acc.y += pA * vA.y + pB * vB.y;
            acc.z += pA * vA.z + pB * vB.z;
            acc.w += pA * vA.w + pB * vB.w;
        }

        // Reduce acc + lsum across the 4 edge-groups (bits 3,4 only).
        // lsum is replicated within each group, so this yields the exact total.
        #pragma unroll
        for (int o = 8; o <= 16; o <<= 1) {
            acc.x += __shfl_xor_sync(FULL, acc.x, o);
            acc.y += __shfl_xor_sync(FULL, acc.y, o);
            acc.z += __shfl_xor_sync(FULL, acc.z, o);
            acc.w += __shfl_xor_sync(FULL, acc.w, o);
            lsum  += __shfl_xor_sync(FULL, lsum,  o);
        }
        const float inv = (lsum > 0.f) ? (1.f / lsum) : 0.f;

        // Transpose agg into smem: lanes 0..7 hold quads 0..7 of the full vector.
        __syncwarp();
        if (lane < 8)
            *reinterpret_cast<float4*>(&sAgg[wib][lane * 4]) = acc;
        __syncwarp();

        // Projection: out[node][lane] = (sum_d agg_d * Wo[d][lane]) * inv + b[lane].
        float o = 0.f;
        #pragma unroll
        for (int qq = 0; qq < 8; ++qq) {
            const float4 a = *reinterpret_cast<const float4*>(&sAgg[wib][qq * 4]);
            o += a.x * sWo[4*qq+0][lane] + a.y * sWo[4*qq+1][lane]
               + a.z * sWo[4*qq+2][lane] + a.w * sWo[4*qq+3][lane];
        }
        out[(size_t)node * ODIM + lane] = o * inv + bval;
    }
}

extern "C" void kernel_launch(void* const* d_in, const int* in_sizes, int n_in,
                              void* d_out, int out_size) {
    const float* X   = (const float*)d_in[0];
    const float* K   = (const float*)d_in[1];
    const float* V   = (const float*)d_in[2];
    const float* Wo  = (const float*)d_in[3];
    const float* bo  = (const float*)d_in[4];
    const int*   src = (const int*)d_in[5];
    const int*   dst = (const int*)d_in[6];

    const int N = in_sizes[0] / DK;   // 100000
    const int E = in_sizes[5];        // 1600000

    build_row_ptr_kernel<<<(E + 255) / 256, 256>>>(dst, E, N);

    const int warps   = (N + NPW - 1) / NPW;          // 50000 warps
    const int threads = 32 * WPB;                     // 128
    const int blocks  = (warps + WPB - 1) / WPB;      // 12500
    gat_kernel<<<blocks, threads>>>(X, K, V, Wo, bo, src, (float*)d_out, N);
}